// round 1
// baseline (speedup 1.0000x reference)
#include <cuda_runtime.h>
#include <cuda_bf16.h>
#include <math.h>

// Problem constants
#define B_    32
#define LQ    300
#define DM    256
#define NH    8
#define HD    32
#define TOTAL 12          // 3 levels x 4 points
#define S_    8400        // 80*80 + 40*40 + 20*20
#define NOFF  (NH * TOTAL * 2)   // 192
#define NATT  (NH * TOTAL)       // 96

// Scratch (device globals: allocation-free)
__device__ float g_loc [B_ * LQ * NOFF];   // (B*Lq, H, 12, 2)
__device__ float g_attn[B_ * LQ * NATT];   // (B*Lq, H, 12)  (softmaxed)

// ---------------------------------------------------------------------------
// Kernel A: per-query projections + softmax + sampling-location computation.
// One block per (b,q), 288 threads: cols 0..191 -> W_off, 192..287 -> W_attn.
// ---------------------------------------------------------------------------
__global__ __launch_bounds__(288)
void proj_kernel(const float* __restrict__ q,
                 const float* __restrict__ ref,     // (B,Lq,1,4)
                 const float* __restrict__ Woff,    // (256,192)
                 const float* __restrict__ boff,
                 const float* __restrict__ Wattn,   // (256,96)
                 const float* __restrict__ battn)
{
    const int bq = blockIdx.x;            // 0 .. B*Lq-1
    const int t  = threadIdx.x;

    __shared__ float sq[DM];
    __shared__ float soff[NOFF];
    __shared__ float sattn[NATT];

    if (t < DM) sq[t] = q[(size_t)bq * DM + t];
    __syncthreads();

    if (t < NOFF) {
        float acc = boff[t];
        #pragma unroll 8
        for (int k = 0; k < DM; k++)
            acc = fmaf(sq[k], Woff[k * NOFF + t], acc);
        soff[t] = acc;
    } else {
        const int c = t - NOFF;           // 0..95
        float acc = battn[c];
        #pragma unroll 8
        for (int k = 0; k < DM; k++)
            acc = fmaf(sq[k], Wattn[k * NATT + c], acc);
        sattn[c] = acc;
    }
    __syncthreads();

    // Softmax over the 12 points of each head (threads 0..7, one head each)
    if (t < NH) {
        float m = -1e30f;
        #pragma unroll
        for (int p = 0; p < TOTAL; p++) m = fmaxf(m, sattn[t * TOTAL + p]);
        float s = 0.f;
        #pragma unroll
        for (int p = 0; p < TOTAL; p++) {
            float e = __expf(sattn[t * TOTAL + p] - m);
            sattn[t * TOTAL + p] = e;
            s += e;
        }
        float inv = 1.0f / s;
        #pragma unroll
        for (int p = 0; p < TOTAL; p++) sattn[t * TOTAL + p] *= inv;
    }
    __syncthreads();

    if (t < NATT) g_attn[(size_t)bq * NATT + t] = sattn[t];

    if (t < NOFF) {
        // loc = ref_xy + off * (1/4) * ref_wh * 0.5  = ref_xy + off*0.125*ref_wh
        const int xy = t & 1;
        const float r  = ref[(size_t)bq * 4 + xy];
        const float wh = ref[(size_t)bq * 4 + 2 + xy];
        g_loc[(size_t)bq * NOFF + t] = fmaf(soff[t] * 0.125f, wh, r);
    }
}

// ---------------------------------------------------------------------------
// Kernel B: bilinear sampling + weighted accumulation.
// One warp per (b,q,h); lane = channel within head (hd=32 == warp size).
// Each corner load is a contiguous 128B warp transaction.
// ---------------------------------------------------------------------------
__global__ __launch_bounds__(256)
void sample_kernel(const float* __restrict__ val,   // input_flatten (B,S,256)
                   float* __restrict__ out)
{
    const int gwarp = (blockIdx.x * blockDim.x + threadIdx.x) >> 5;
    const int lane  = threadIdx.x & 31;
    if (gwarp >= B_ * LQ * NH) return;

    const int bq = gwarp >> 3;            // b*Lq + q
    const int h  = gwarp & 7;
    const int b  = bq / LQ;

    const float* vbase = val + (size_t)b * S_ * DM + h * HD + lane;
    const float* locp  = g_loc  + (size_t)bq * NOFF + h * (TOTAL * 2);
    const float* attnp = g_attn + (size_t)bq * NATT + h * TOTAL;

    const int   dims[3]   = {80, 40, 20};
    const int   starts[3] = {0, 6400, 8000};

    float acc = 0.f;

    #pragma unroll
    for (int p = 0; p < TOTAL; p++) {
        const int l = p >> 2;
        const int W = dims[l];
        const int H = dims[l];
        const int st = starts[l];

        const float lx = locp[2 * p];
        const float ly = locp[2 * p + 1];
        const float w  = attnp[p];

        // grid = 2*loc - 1 ; ix = ((gx+1)*W - 1)*0.5  ==  loc*W - 0.5
        const float ix = lx * (float)W - 0.5f;
        const float iy = ly * (float)H - 0.5f;

        const int x0 = (int)floorf(ix);
        const int y0 = (int)floorf(iy);
        const int x1 = x0 + 1;
        const int y1 = y0 + 1;
        const float fx = ix - (float)x0;
        const float fy = iy - (float)y0;

        const bool vx0 = (x0 >= 0) & (x0 < W);
        const bool vx1 = (x1 >= 0) & (x1 < W);
        const bool vy0 = (y0 >= 0) & (y0 < H);
        const bool vy1 = (y1 >= 0) & (y1 < H);

        float v00 = 0.f, v01 = 0.f, v10 = 0.f, v11 = 0.f;
        if (vx0 & vy0) v00 = vbase[(size_t)(st + y0 * W + x0) * DM];
        if (vx1 & vy0) v01 = vbase[(size_t)(st + y0 * W + x1) * DM];
        if (vx0 & vy1) v10 = vbase[(size_t)(st + y1 * W + x0) * DM];
        if (vx1 & vy1) v11 = vbase[(size_t)(st + y1 * W + x1) * DM];

        const float s = (1.f - fx) * (1.f - fy) * v00
                      +        fx  * (1.f - fy) * v01
                      + (1.f - fx) *        fy  * v10
                      +        fx  *        fy  * v11;
        acc = fmaf(w, s, acc);
    }

    out[(size_t)bq * DM + h * HD + lane] = acc;
}

// ---------------------------------------------------------------------------
// Launch
// ---------------------------------------------------------------------------
extern "C" void kernel_launch(void* const* d_in, const int* in_sizes, int n_in,
                              void* d_out, int out_size)
{
    const float* query = (const float*)d_in[0];
    const float* ref   = (const float*)d_in[1];
    const float* value = (const float*)d_in[2];
    const float* Woff  = (const float*)d_in[3];
    const float* boff  = (const float*)d_in[4];
    const float* Wattn = (const float*)d_in[5];
    const float* battn = (const float*)d_in[6];
    float* out = (float*)d_out;

    proj_kernel<<<B_ * LQ, 288>>>(query, ref, Woff, boff, Wattn, battn);

    const int nwarps  = B_ * LQ * NH;           // 76800
    const int threads = 256;                    // 8 warps / block
    const int blocks  = (nwarps * 32 + threads - 1) / threads;
    sample_kernel<<<blocks, threads>>>(value, out);
}

// round 3
// speedup vs baseline: 1.5804x; 1.5804x over previous
#include <cuda_runtime.h>
#include <cuda_bf16.h>
#include <math.h>

// Problem constants
#define B_    32
#define LQ    300
#define DM    256
#define NH    8
#define HD    32
#define TOTAL 12          // 3 levels x 4 points
#define S_    8400        // 80*80 + 40*40 + 20*20
#define NOFF  (NH * TOTAL * 2)   // 192
#define NATT  (NH * TOTAL)       // 96

#define QB    32                 // queries per proj block
#define SQ_STRIDE   36           // floats per k-row (16B aligned rows)
#define SRES_STRIDE 289          // 288 outputs + 1 pad

typedef unsigned long long ull;

// Descriptor scratch: per (bq, h, p) -> 4 gather offsets + 4 premultiplied weights
__device__ int4   g_idx[B_ * LQ * NATT];
__device__ float4 g_w  [B_ * LQ * NATT];

__device__ __forceinline__ ull pack2(float lo, float hi) {
    ull r; asm("mov.b64 %0, {%1, %2};" : "=l"(r) : "f"(lo), "f"(hi)); return r;
}
__device__ __forceinline__ void unpack2(ull v, float& lo, float& hi) {
    asm("mov.b64 {%0, %1}, %2;" : "=f"(lo), "=f"(hi) : "l"(v));
}
__device__ __forceinline__ ull fma2(ull a, ull b, ull c) {
    ull d; asm("fma.rn.f32x2 %0, %1, %2, %3;" : "=l"(d) : "l"(a), "l"(b), "l"(c)); return d;
}

// ---------------------------------------------------------------------------
// Kernel A: tiled projection GEMM (QB queries x 288 cols) + softmax +
// full sampling-descriptor precomputation.
// ---------------------------------------------------------------------------
__global__ __launch_bounds__(288)
void proj_kernel(const float* __restrict__ q,
                 const float* __restrict__ ref,     // (B,Lq,1,4)
                 const float* __restrict__ Woff,    // (256,192)
                 const float* __restrict__ boff,
                 const float* __restrict__ Wattn,   // (256,96)
                 const float* __restrict__ battn)
{
    const int t   = threadIdx.x;
    const int bq0 = blockIdx.x * QB;

    // sbuf is reused: phase 1-2 = transposed query tile, phase 3+ = results
    __shared__ __align__(16) float sbuf[QB * SRES_STRIDE];  // 9248 >= 256*36
    __shared__ float sref[QB][4];

    // --- load query tile transposed: sbuf[k*36 + qi] ---
    for (int i = t; i < QB * DM; i += 288) {
        const int qi = i >> 8;
        const int k  = i & 255;
        sbuf[k * SQ_STRIDE + qi] = q[(size_t)(bq0 + qi) * DM + k];
    }
    if (t < QB * 4) sref[t >> 2][t & 3] = ref[(size_t)bq0 * 4 + t];
    __syncthreads();

    // --- GEMM: thread t owns output column t for all QB queries ---
    const float* Wcol; int stride; float bias;
    if (t < NOFF) { Wcol = Woff  + t;        stride = NOFF; bias = boff[t]; }
    else          { Wcol = Wattn + (t-NOFF); stride = NATT; bias = battn[t-NOFF]; }

    ull acc[QB / 2];
    {
        const ull b2 = pack2(bias, bias);
        #pragma unroll
        for (int j = 0; j < QB / 2; j++) acc[j] = b2;
    }

    #pragma unroll 4
    for (int k = 0; k < DM; k++) {
        const float w = Wcol[k * stride];
        const ull  wp = pack2(w, w);
        const ulonglong2* row = (const ulonglong2*)(sbuf + k * SQ_STRIDE);
        #pragma unroll
        for (int j = 0; j < 8; j++) {
            ulonglong2 s = row[j];                 // 4 queries (LDS.128)
            acc[2*j]   = fma2(s.x, wp, acc[2*j]);
            acc[2*j+1] = fma2(s.y, wp, acc[2*j+1]);
        }
    }
    __syncthreads();   // everyone done reading query tile

    // --- write results: sres[q][t] ---
    float* sres = sbuf;
    #pragma unroll
    for (int j = 0; j < QB / 2; j++) {
        float lo, hi; unpack2(acc[j], lo, hi);
        sres[(2*j)   * SRES_STRIDE + t] = lo;
        sres[(2*j+1) * SRES_STRIDE + t] = hi;
    }
    __syncthreads();

    // --- softmax over the 12 points of each (q, h) ---
    if (t < QB * NH) {
        float* a = sres + (t >> 3) * SRES_STRIDE + NOFF + (t & 7) * TOTAL;
        float m = -1e30f;
        #pragma unroll
        for (int p = 0; p < TOTAL; p++) m = fmaxf(m, a[p]);
        float s = 0.f;
        #pragma unroll
        for (int p = 0; p < TOTAL; p++) { float e = __expf(a[p] - m); a[p] = e; s += e; }
        const float inv = 1.0f / s;
        #pragma unroll
        for (int p = 0; p < TOTAL; p++) a[p] *= inv;
    }
    __syncthreads();

    // --- descriptors: per (q, h, p) compute 4 offsets + 4 premult weights ---
    const int   dims[3]   = {80, 40, 20};
    const int   starts[3] = {0, 6400, 8000};

    for (int d = t; d < QB * NATT; d += 288) {
        const int qi  = d / NATT;
        const int rem = d - qi * NATT;
        const int h   = rem / TOTAL;
        const int p   = rem - h * TOTAL;

        const float* sr = sref[qi];
        const float offx = sres[qi * SRES_STRIDE + h * (TOTAL*2) + 2*p];
        const float offy = sres[qi * SRES_STRIDE + h * (TOTAL*2) + 2*p + 1];
        const float wt   = sres[qi * SRES_STRIDE + NOFF + h * TOTAL + p];

        // loc = ref_xy + off * 0.125 * ref_wh ;  ix = loc*W - 0.5
        const float lx = fmaf(offx * 0.125f, sr[2], sr[0]);
        const float ly = fmaf(offy * 0.125f, sr[3], sr[1]);

        const int lvl = p >> 2;
        const int W   = dims[lvl];
        const int st  = starts[lvl];

        const float ix = lx * (float)W - 0.5f;
        const float iy = ly * (float)W - 0.5f;
        const float fix = floorf(ix);
        const float fiy = floorf(iy);
        const int x0 = (int)fix, y0 = (int)fiy;
        const int x1 = x0 + 1,   y1 = y0 + 1;
        const float fx = ix - fix;
        const float fy = iy - fiy;

        const bool vx0 = (x0 >= 0) & (x0 < W);
        const bool vx1 = (x1 >= 0) & (x1 < W);
        const bool vy0 = (y0 >= 0) & (y0 < W);
        const bool vy1 = (y1 >= 0) & (y1 < W);

        const int bq = bq0 + qi;
        const int b  = bq / LQ;
        const int base = b * S_ + st;

        const int xc0 = min(max(x0, 0), W - 1);
        const int xc1 = min(max(x1, 0), W - 1);
        const int yc0 = min(max(y0, 0), W - 1);
        const int yc1 = min(max(y1, 0), W - 1);

        int4 id;
        id.x = (vx0 & vy0) ? (base + yc0 * W + xc0) * DM : 0;
        id.y = (vx1 & vy0) ? (base + yc0 * W + xc1) * DM : 0;
        id.z = (vx0 & vy1) ? (base + yc1 * W + xc0) * DM : 0;
        id.w = (vx1 & vy1) ? (base + yc1 * W + xc1) * DM : 0;

        float4 ww;
        ww.x = (vx0 & vy0) ? wt * (1.f - fx) * (1.f - fy) : 0.f;
        ww.y = (vx1 & vy0) ? wt *        fx  * (1.f - fy) : 0.f;
        ww.z = (vx0 & vy1) ? wt * (1.f - fx) *        fy  : 0.f;
        ww.w = (vx1 & vy1) ? wt *        fx  *        fy  : 0.f;

        const int gd = (bq * NH + h) * TOTAL + p;
        g_idx[gd] = id;
        g_w[gd]   = ww;
    }
}

// ---------------------------------------------------------------------------
// Kernel B: pure gather + FMA. One warp per (bq, h); lane = channel.
// ---------------------------------------------------------------------------
__global__ __launch_bounds__(256)
void sample_kernel(const float* __restrict__ val,   // input_flatten (B,S,256)
                   float* __restrict__ out)
{
    const int gwarp = (blockIdx.x * blockDim.x + threadIdx.x) >> 5;
    const int lane  = threadIdx.x & 31;
    if (gwarp >= B_ * LQ * NH) return;

    const int h = gwarp & 7;
    const float* vb = val + h * HD + lane;     // batch folded into idx
    const int dbase = gwarp * TOTAL;

    float acc = 0.f;

    #pragma unroll
    for (int p = 0; p < TOTAL; p++) {
        const int4   id = __ldg(&g_idx[dbase + p]);
        const float4 ww = __ldg(&g_w  [dbase + p]);
        acc = fmaf(ww.x, __ldg(vb + id.x), acc);
        acc = fmaf(ww.y, __ldg(vb + id.y), acc);
        acc = fmaf(ww.z, __ldg(vb + id.z), acc);
        acc = fmaf(ww.w, __ldg(vb + id.w), acc);
    }

    out[(size_t)(gwarp >> 3) * DM + h * HD + lane] = acc;
}

// ---------------------------------------------------------------------------
// Launch
// ---------------------------------------------------------------------------
extern "C" void kernel_launch(void* const* d_in, const int* in_sizes, int n_in,
                              void* d_out, int out_size)
{
    const float* query = (const float*)d_in[0];
    const float* ref   = (const float*)d_in[1];
    const float* value = (const float*)d_in[2];
    const float* Woff  = (const float*)d_in[3];
    const float* boff  = (const float*)d_in[4];
    const float* Wattn = (const float*)d_in[5];
    const float* battn = (const float*)d_in[6];
    float* out = (float*)d_out;

    proj_kernel<<<(B_ * LQ) / QB, 288>>>(query, ref, Woff, boff, Wattn, battn);

    const int nwarps  = B_ * LQ * NH;           // 76800
    const int threads = 256;
    const int blocks  = (nwarps * 32 + threads - 1) / threads;
    sample_kernel<<<blocks, threads>>>(value, out);
}

// round 6
// speedup vs baseline: 1.7725x; 1.1216x over previous
#include <cuda_runtime.h>
#include <cuda_bf16.h>
#include <math.h>

// Problem constants
#define B_    32
#define LQ    300
#define DM    256
#define NH    8
#define HD    32
#define TOTAL 12          // 3 levels x 4 points
#define S_    8400        // 80*80 + 40*40 + 20*20
#define NOFF  (NH * TOTAL * 2)   // 192
#define NATT  (NH * TOTAL)       // 96

#define QB    16                 // queries per proj block
#define SQ_STRIDE   20           // floats per k-row (16B aligned rows: 80B)
#define SRES_STRIDE 289          // 288 outputs + 1 pad
#define SBUF_FLOATS 5120         // max(256*20, 16*289)

typedef unsigned long long ull;

// Descriptor scratch: per (bq, h, p):
//   g_bflag = clamped base element index (multiple of 256) | bit0: x-step valid | bit1: y-step valid
//   g_wquad = {fx0, fx1, fy0*wt, fy1*wt} with validity folded in (invalid -> 0)
__device__ int    g_bflag[B_ * LQ * NATT];
__device__ float4 g_wquad[B_ * LQ * NATT];

__device__ __forceinline__ ull pack2(float lo, float hi) {
    ull r; asm("mov.b64 %0, {%1, %2};" : "=l"(r) : "f"(lo), "f"(hi)); return r;
}
__device__ __forceinline__ void unpack2(ull v, float& lo, float& hi) {
    asm("mov.b64 {%0, %1}, %2;" : "=f"(lo), "=f"(hi) : "l"(v));
}
__device__ __forceinline__ ull fma2(ull a, ull b, ull c) {
    ull d; asm("fma.rn.f32x2 %0, %1, %2, %3;" : "=l"(d) : "l"(a), "l"(b), "l"(c)); return d;
}

// ---------------------------------------------------------------------------
// Kernel A: tiled projection GEMM (QB queries x 288 cols) + softmax +
// sampling-descriptor precomputation (validity folded into weights).
// ---------------------------------------------------------------------------
__global__ __launch_bounds__(288)
void proj_kernel(const float* __restrict__ q,
                 const float* __restrict__ ref,     // (B,Lq,1,4)
                 const float* __restrict__ Woff,    // (256,192)
                 const float* __restrict__ boff,
                 const float* __restrict__ Wattn,   // (256,96)
                 const float* __restrict__ battn)
{
    const int t   = threadIdx.x;
    const int bq0 = blockIdx.x * QB;

    // sbuf reused: phase 1-2 = transposed query tile, phase 3+ = results
    __shared__ __align__(16) float sbuf[SBUF_FLOATS];
    __shared__ float sref[QB][4];

    // --- load query tile transposed: sbuf[k*20 + qi] ---
    for (int i = t; i < QB * DM; i += 288) {
        const int qi = i >> 8;
        const int k  = i & 255;
        sbuf[k * SQ_STRIDE + qi] = q[(size_t)(bq0 + qi) * DM + k];
    }
    if (t < QB * 4) sref[t >> 2][t & 3] = ref[(size_t)bq0 * 4 + t];
    __syncthreads();

    // --- GEMM: thread t owns output column t for all QB queries ---
    const float* Wcol; int stride; float bias;
    if (t < NOFF) { Wcol = Woff  + t;        stride = NOFF; bias = boff[t]; }
    else          { Wcol = Wattn + (t-NOFF); stride = NATT; bias = battn[t-NOFF]; }

    ull acc[QB / 2];
    {
        const ull b2 = pack2(bias, bias);
        #pragma unroll
        for (int j = 0; j < QB / 2; j++) acc[j] = b2;
    }

    #pragma unroll 8
    for (int k = 0; k < DM; k++) {
        const float w = Wcol[k * stride];
        const ull  wp = pack2(w, w);
        const ulonglong2* row = (const ulonglong2*)(sbuf + k * SQ_STRIDE);
        #pragma unroll
        for (int j = 0; j < QB / 4; j++) {
            ulonglong2 s = row[j];                 // 4 queries (LDS.128)
            acc[2*j]   = fma2(s.x, wp, acc[2*j]);
            acc[2*j+1] = fma2(s.y, wp, acc[2*j+1]);
        }
    }
    __syncthreads();   // everyone done reading query tile

    // --- write results: sres[q][t] ---
    float* sres = sbuf;
    #pragma unroll
    for (int j = 0; j < QB / 2; j++) {
        float lo, hi; unpack2(acc[j], lo, hi);
        sres[(2*j)   * SRES_STRIDE + t] = lo;
        sres[(2*j+1) * SRES_STRIDE + t] = hi;
    }
    __syncthreads();

    // --- softmax over the 12 points of each (q, h) ---
    if (t < QB * NH) {
        float* a = sres + (t >> 3) * SRES_STRIDE + NOFF + (t & 7) * TOTAL;
        float m = -1e30f;
        #pragma unroll
        for (int p = 0; p < TOTAL; p++) m = fmaxf(m, a[p]);
        float s = 0.f;
        #pragma unroll
        for (int p = 0; p < TOTAL; p++) { float e = __expf(a[p] - m); a[p] = e; s += e; }
        const float inv = 1.0f / s;
        #pragma unroll
        for (int p = 0; p < TOTAL; p++) a[p] *= inv;
    }
    __syncthreads();

    // --- descriptors ---
    for (int d = t; d < QB * NATT; d += 288) {
        const int qi  = d / NATT;
        const int rem = d - qi * NATT;
        const int h   = rem / TOTAL;
        const int p   = rem - h * TOTAL;

        const float* sr = sref[qi];
        const float offx = sres[qi * SRES_STRIDE + h * (TOTAL*2) + 2*p];
        const float offy = sres[qi * SRES_STRIDE + h * (TOTAL*2) + 2*p + 1];
        const float wt   = sres[qi * SRES_STRIDE + NOFF + h * TOTAL + p];

        // loc = ref_xy + off * 0.125 * ref_wh ;  ix = loc*W - 0.5
        const float lx = fmaf(offx * 0.125f, sr[2], sr[0]);
        const float ly = fmaf(offy * 0.125f, sr[3], sr[1]);

        const int lvl = p >> 2;
        const int W   = 80 >> lvl;
        const int st  = (lvl == 0) ? 0 : ((lvl == 1) ? 6400 : 8000);

        const float ix = lx * (float)W - 0.5f;
        const float iy = ly * (float)W - 0.5f;
        const float fix = floorf(ix);
        const float fiy = floorf(iy);
        const int x0 = (int)fix, y0 = (int)fiy;
        const int x1 = x0 + 1,   y1 = y0 + 1;
        const float fx = ix - fix;
        const float fy = iy - fiy;

        const bool vx0 = (x0 >= 0) & (x0 < W);
        const bool vx1 = (x1 >= 0) & (x1 < W);
        const bool vy0 = (y0 >= 0) & (y0 < W);
        const bool vy1 = (y1 >= 0) & (y1 < W);

        const int bq = bq0 + qi;
        const int b  = bq / LQ;

        const int xc0 = min(max(x0, 0), W - 1);
        const int yc0 = min(max(y0, 0), W - 1);

        int bflag = (b * S_ + st + yc0 * W + xc0) * DM;
        if (vx0 & vx1) bflag |= 1;
        if (vy0 & vy1) bflag |= 2;

        float4 wq;
        wq.x = vx0 ? (1.f - fx) : 0.f;            // fx0
        wq.y = vx1 ? fx         : 0.f;            // fx1
        wq.z = (vy0 ? (1.f - fy) : 0.f) * wt;     // fy0*wt
        wq.w = (vy1 ? fy         : 0.f) * wt;     // fy1*wt

        const int gd = (bq * NH + h) * TOTAL + p;
        g_bflag[gd] = bflag;
        g_wquad[gd] = wq;
    }
}

// ---------------------------------------------------------------------------
// Kernel B: gather + FMA. One warp per (bq, h); lane = channel.
// Descriptors loaded cooperatively by lanes 0..11 (3 wavefronts), then shfl.
// ---------------------------------------------------------------------------
__global__ __launch_bounds__(256)
void sample_kernel(const float* __restrict__ val,   // input_flatten (B,S,256)
                   float* __restrict__ out)
{
    const int gwarp = (blockIdx.x * blockDim.x + threadIdx.x) >> 5;
    const int lane  = threadIdx.x & 31;
    if (gwarp >= B_ * LQ * NH) return;

    const int h = gwarp & 7;
    const float* vb = val + h * HD + lane;     // batch folded into base index
    const int dbase = gwarp * TOTAL;

    int    bf = 0;
    float4 wq = make_float4(0.f, 0.f, 0.f, 0.f);
    if (lane < TOTAL) {
        bf = __ldg(&g_bflag[dbase + lane]);
        wq = __ldg(&g_wquad[dbase + lane]);
    }

    float acc = 0.f;

    #pragma unroll
    for (int p = 0; p < TOTAL; p++) {
        const int lvl = p >> 2;
        const int dyv = (80 >> lvl) * DM;

        const int   bfp = __shfl_sync(0xffffffffu, bf,   p);
        const float fx0 = __shfl_sync(0xffffffffu, wq.x, p);
        const float fx1 = __shfl_sync(0xffffffffu, wq.y, p);
        const float fy0 = __shfl_sync(0xffffffffu, wq.z, p);
        const float fy1 = __shfl_sync(0xffffffffu, wq.w, p);

        const int base = bfp & ~255;
        const int dx   = (bfp & 1) ? DM  : 0;
        const int dy   = (bfp & 2) ? dyv : 0;

        const float v00 = __ldg(vb + base);
        const float v01 = __ldg(vb + base + dx);
        const float v10 = __ldg(vb + base + dy);
        const float v11 = __ldg(vb + base + dx + dy);

        acc = fmaf(fx0 * fy0, v00, acc);
        acc = fmaf(fx1 * fy0, v01, acc);
        acc = fmaf(fx0 * fy1, v10, acc);
        acc = fmaf(fx1 * fy1, v11, acc);
    }

    out[(size_t)(gwarp >> 3) * DM + h * HD + lane] = acc;
}

// ---------------------------------------------------------------------------
// Launch
// ---------------------------------------------------------------------------
extern "C" void kernel_launch(void* const* d_in, const int* in_sizes, int n_in,
                              void* d_out, int out_size)
{
    const float* query = (const float*)d_in[0];
    const float* ref   = (const float*)d_in[1];
    const float* value = (const float*)d_in[2];
    const float* Woff  = (const float*)d_in[3];
    const float* boff  = (const float*)d_in[4];
    const float* Wattn = (const float*)d_in[5];
    const float* battn = (const float*)d_in[6];
    float* out = (float*)d_out;

    proj_kernel<<<(B_ * LQ) / QB, 288>>>(query, ref, Woff, boff, Wattn, battn);

    const int nwarps  = B_ * LQ * NH;           // 76800
    const int threads = 256;
    const int blocks  = (nwarps * 32 + threads - 1) / threads;
    sample_kernel<<<blocks, threads>>>(value, out);
}

// round 7
// speedup vs baseline: 1.9261x; 1.0867x over previous
#include <cuda_runtime.h>
#include <cuda_bf16.h>
#include <math.h>

// Problem constants
#define B_    32
#define LQ    300
#define DM    256
#define NH    8
#define HD    32
#define TOTAL 12          // 3 levels x 4 points
#define S_    8400        // 80*80 + 40*40 + 20*20
#define NOFF  (NH * TOTAL * 2)   // 192
#define NATT  (NH * TOTAL)       // 96
#define NCOL  (NOFF + NATT)      // 288

// GEMM tiling
#define BM 64
#define BN 96
#define BK 16
#define QS_STRIDE 68      // 64 + pad4: 16B-aligned rows, <=2-way STS conflicts

typedef unsigned long long ull;

// Scratch
__device__ float  g_res  [B_ * LQ * NCOL];   // projection outputs (9600 x 288)
__device__ int    g_bflag[B_ * LQ * NATT];   // clamped base | dx-valid | dy-valid
__device__ float4 g_wquad[B_ * LQ * NATT];   // premultiplied corner weights

__device__ __forceinline__ ull pack2(float lo, float hi) {
    ull r; asm("mov.b64 %0, {%1, %2};" : "=l"(r) : "f"(lo), "f"(hi)); return r;
}
__device__ __forceinline__ void unpack2(ull v, float& lo, float& hi) {
    asm("mov.b64 {%0, %1}, %2;" : "=f"(lo), "=f"(hi) : "l"(v));
}
__device__ __forceinline__ ull fma2(ull a, ull b, ull c) {
    ull d; asm("fma.rn.f32x2 %0, %1, %2, %3;" : "=l"(d) : "l"(a), "l"(b), "l"(c)); return d;
}

// ---------------------------------------------------------------------------
// Kernel A: tiled SGEMM  C[9600,288] = Q[9600,256] * W[256,288] + bias
// Block: BM x BN tile, 256 threads, micro-tile 8M x 3N, f32x2 FMAs.
// ---------------------------------------------------------------------------
__global__ __launch_bounds__(256)
void gemm_kernel(const float* __restrict__ q,
                 const float* __restrict__ Woff,    // (256,192)
                 const float* __restrict__ boff,
                 const float* __restrict__ Wattn,   // (256,96)
                 const float* __restrict__ battn)
{
    const int t   = threadIdx.x;
    const int bm0 = blockIdx.x * BM;
    const int bn  = blockIdx.y;                  // 0,1 -> Woff halves; 2 -> Wattn

    __shared__ __align__(16) float Qs[BK * QS_STRIDE];  // transposed [k][m]
    __shared__ float Ws[BK * BN];                       // natural    [k][n]

    const float* Wg; int wstride; const float* bg;
    if (bn < 2) { Wg = Woff + bn * BN; wstride = NOFF; bg = boff + bn * BN; }
    else        { Wg = Wattn;          wstride = NATT; bg = battn; }

    const int tn = t & 31;           // col group
    const int tm = t >> 5;           // row group (0..7), 8 rows each

    // W chunk load mapping (6 scalars/thread), precomputed
    int wk[6], wn[6];
    #pragma unroll
    for (int i = 0; i < 6; i++) {
        const int flat = t + i * 256;
        wk[i] = flat / BN;
        wn[i] = flat - wk[i] * BN;
    }
    // Q chunk load mapping (1 float4/thread)
    const int qr  = t >> 2;          // row 0..63
    const int qc4 = t & 3;           // k-chunk-of-4

    // accumulators: acc[j][pair], pair over M
    ull acc[3][4];
    #pragma unroll
    for (int j = 0; j < 3; j++) {
        const float b = bg[tn + 32 * j];
        const ull b2 = pack2(b, b);
        #pragma unroll
        for (int pi = 0; pi < 4; pi++) acc[j][pi] = b2;
    }

    // preload chunk 0
    float4 rq = *(const float4*)(q + (size_t)(bm0 + qr) * DM + qc4 * 4);
    float rw[6];
    #pragma unroll
    for (int i = 0; i < 6; i++) rw[i] = Wg[wk[i] * wstride + wn[i]];

    const int NCH = DM / BK;         // 16 chunks
    for (int ch = 0; ch < NCH; ch++) {
        // store current chunk to smem
        Qs[(qc4 * 4 + 0) * QS_STRIDE + qr] = rq.x;
        Qs[(qc4 * 4 + 1) * QS_STRIDE + qr] = rq.y;
        Qs[(qc4 * 4 + 2) * QS_STRIDE + qr] = rq.z;
        Qs[(qc4 * 4 + 3) * QS_STRIDE + qr] = rq.w;
        #pragma unroll
        for (int i = 0; i < 6; i++) Ws[wk[i] * BN + wn[i]] = rw[i];
        __syncthreads();

        // prefetch next chunk
        if (ch + 1 < NCH) {
            const int k0 = (ch + 1) * BK;
            rq = *(const float4*)(q + (size_t)(bm0 + qr) * DM + k0 + qc4 * 4);
            #pragma unroll
            for (int i = 0; i < 6; i++) rw[i] = Wg[(k0 + wk[i]) * wstride + wn[i]];
        }

        // compute
        #pragma unroll
        for (int kk = 0; kk < BK; kk++) {
            const float* qrow = Qs + kk * QS_STRIDE + tm * 8;
            const ulonglong2 qa = *(const ulonglong2*)qrow;        // m pairs 01,23
            const ulonglong2 qb = *(const ulonglong2*)(qrow + 4);  // m pairs 45,67
            #pragma unroll
            for (int j = 0; j < 3; j++) {
                const float w = Ws[kk * BN + tn + 32 * j];
                const ull  wp = pack2(w, w);
                acc[j][0] = fma2(qa.x, wp, acc[j][0]);
                acc[j][1] = fma2(qa.y, wp, acc[j][1]);
                acc[j][2] = fma2(qb.x, wp, acc[j][2]);
                acc[j][3] = fma2(qb.y, wp, acc[j][3]);
            }
        }
        __syncthreads();
    }

    // epilogue: coalesced stores
    #pragma unroll
    for (int j = 0; j < 3; j++) {
        const int n = bn * BN + tn + 32 * j;
        #pragma unroll
        for (int pi = 0; pi < 4; pi++) {
            float lo, hi; unpack2(acc[j][pi], lo, hi);
            const int m = bm0 + tm * 8 + 2 * pi;
            g_res[(size_t)m       * NCOL + n] = lo;
            g_res[(size_t)(m + 1) * NCOL + n] = hi;
        }
    }
}

// ---------------------------------------------------------------------------
// Kernel B: softmax + sampling descriptors. One thread per (bq, h).
// ---------------------------------------------------------------------------
__global__ __launch_bounds__(256)
void desc_kernel(const float* __restrict__ ref)    // (B,Lq,1,4)
{
    const int tid = blockIdx.x * blockDim.x + threadIdx.x;
    if (tid >= B_ * LQ * NH) return;
    const int bq = tid >> 3;
    const int h  = tid & 7;
    const int b  = bq / LQ;

    const float4 r4 = __ldg((const float4*)(ref + (size_t)bq * 4));
    const float* row = g_res + (size_t)bq * NCOL;

    // softmax over the 12 attn logits
    float a[TOTAL];
    float m = -1e30f;
    #pragma unroll
    for (int p = 0; p < TOTAL; p++) { a[p] = row[NOFF + h * TOTAL + p]; m = fmaxf(m, a[p]); }
    float s = 0.f;
    #pragma unroll
    for (int p = 0; p < TOTAL; p++) { a[p] = __expf(a[p] - m); s += a[p]; }
    const float inv = 1.0f / s;

    const int dbase = tid * TOTAL;
    #pragma unroll
    for (int p = 0; p < TOTAL; p++) {
        const float offx = row[h * (TOTAL * 2) + 2 * p];
        const float offy = row[h * (TOTAL * 2) + 2 * p + 1];
        const float wt   = a[p] * inv;

        const float lx = fmaf(offx * 0.125f, r4.z, r4.x);
        const float ly = fmaf(offy * 0.125f, r4.w, r4.y);

        const int lvl = p >> 2;
        const int W   = 80 >> lvl;
        const int st  = (lvl == 0) ? 0 : ((lvl == 1) ? 6400 : 8000);

        const float ix = lx * (float)W - 0.5f;
        const float iy = ly * (float)W - 0.5f;
        const float fix = floorf(ix);
        const float fiy = floorf(iy);
        const int x0 = (int)fix, y0 = (int)fiy;
        const float fx = ix - fix;
        const float fy = iy - fiy;

        const bool vx0 = (x0 >= 0)     & (x0 < W);
        const bool vx1 = (x0 >= -1)    & (x0 < W - 1);
        const bool vy0 = (y0 >= 0)     & (y0 < W);
        const bool vy1 = (y0 >= -1)    & (y0 < W - 1);

        const int xc0 = min(max(x0, 0), W - 1);
        const int yc0 = min(max(y0, 0), W - 1);

        int bflag = (b * S_ + st + yc0 * W + xc0) * DM;
        if (vx0 & vx1) bflag |= 1;
        if (vy0 & vy1) bflag |= 2;

        const float fx0 = vx0 ? (1.f - fx) : 0.f;
        const float fx1 = vx1 ? fx         : 0.f;
        const float fy0 = (vy0 ? (1.f - fy) : 0.f) * wt;
        const float fy1 = (vy1 ? fy         : 0.f) * wt;

        float4 wq;
        wq.x = fx0 * fy0;   // w00
        wq.y = fx1 * fy0;   // w01
        wq.z = fx0 * fy1;   // w10
        wq.w = fx1 * fy1;   // w11

        g_bflag[dbase + p] = bflag;
        g_wquad[dbase + p] = wq;
    }
}

// ---------------------------------------------------------------------------
// Kernel C: gather + FMA. One warp per (bq, h); lane = channel.
// Descriptors staged in smem (block = 8 tasks), read via broadcast LDS.
// ---------------------------------------------------------------------------
__global__ __launch_bounds__(256)
void sample_kernel(const float* __restrict__ val,   // input_flatten (B,S,256)
                   float* __restrict__ out)
{
    __shared__ int    sbf[8 * TOTAL];
    __shared__ float4 swq[8 * TOTAL];

    const int t     = threadIdx.x;
    const int task0 = blockIdx.x * 8;

    if (t < 8 * TOTAL) {
        sbf[t] = __ldg(&g_bflag[task0 * TOTAL + t]);
        swq[t] = __ldg(&g_wquad[task0 * TOTAL + t]);
    }
    __syncthreads();

    const int w    = t >> 5;
    const int lane = t & 31;
    const int task = task0 + w;
    const int h    = task & 7;

    const float* vb = val + h * HD + lane;

    float acc = 0.f;

    #pragma unroll
    for (int p = 0; p < TOTAL; p++) {
        const int lvl = p >> 2;
        const int dyv = (80 >> lvl) * DM;

        const int    bf = sbf[w * TOTAL + p];
        const float4 ww = swq[w * TOTAL + p];

        const int base = bf & ~255;
        const int dx   = (bf & 1) ? DM  : 0;
        const int dy   = (bf & 2) ? dyv : 0;

        const float v00 = __ldg(vb + base);
        const float v01 = __ldg(vb + base + dx);
        const float v10 = __ldg(vb + base + dy);
        const float v11 = __ldg(vb + base + dx + dy);

        acc = fmaf(ww.x, v00, acc);
        acc = fmaf(ww.y, v01, acc);
        acc = fmaf(ww.z, v10, acc);
        acc = fmaf(ww.w, v11, acc);
    }

    out[(size_t)(task >> 3) * DM + h * HD + lane] = acc;
}

// ---------------------------------------------------------------------------
// Launch
// ---------------------------------------------------------------------------
extern "C" void kernel_launch(void* const* d_in, const int* in_sizes, int n_in,
                              void* d_out, int out_size)
{
    const float* query = (const float*)d_in[0];
    const float* ref   = (const float*)d_in[1];
    const float* value = (const float*)d_in[2];
    const float* Woff  = (const float*)d_in[3];
    const float* boff  = (const float*)d_in[4];
    const float* Wattn = (const float*)d_in[5];
    const float* battn = (const float*)d_in[6];
    float* out = (float*)d_out;

    dim3 ggrid(B_ * LQ / BM, 3);                     // 150 x 3
    gemm_kernel<<<ggrid, 256>>>(query, Woff, boff, Wattn, battn);

    desc_kernel<<<(B_ * LQ * NH + 255) / 256, 256>>>(ref);

    sample_kernel<<<B_ * LQ, 256>>>(value, out);     // 9600 blocks, 8 tasks each
}

// round 8
// speedup vs baseline: 2.1279x; 1.1048x over previous
#include <cuda_runtime.h>
#include <cuda_bf16.h>
#include <math.h>

// Problem constants
#define B_    32
#define LQ    300
#define DM    256
#define NH    8
#define HD    32
#define TOTAL 12          // 3 levels x 4 points
#define S_    8400        // 80*80 + 40*40 + 20*20
#define NOFF  (NH * TOTAL * 2)   // 192
#define NATT  (NH * TOTAL)       // 96
#define NCOL  (NOFF + NATT)      // 288

// GEMM tiling
#define BM 64
#define BN 96
#define BK 16
#define QS_STRIDE 68      // 64 + pad4

typedef unsigned long long ull;

// Scratch
__device__ float  g_res  [B_ * LQ * NCOL];   // projection outputs (9600 x 288)
__device__ int    g_bflag[B_ * LQ * NATT];   // clamped base | dx-valid | dy-valid
__device__ float4 g_wquad[B_ * LQ * NATT];   // premultiplied corner weights

__device__ __forceinline__ ull pack2(float lo, float hi) {
    ull r; asm("mov.b64 %0, {%1, %2};" : "=l"(r) : "f"(lo), "f"(hi)); return r;
}
__device__ __forceinline__ void unpack2(ull v, float& lo, float& hi) {
    asm("mov.b64 {%0, %1}, %2;" : "=f"(lo), "=f"(hi) : "l"(v));
}
__device__ __forceinline__ ull fma2(ull a, ull b, ull c) {
    ull d; asm("fma.rn.f32x2 %0, %1, %2, %3;" : "=l"(d) : "l"(a), "l"(b), "l"(c)); return d;
}

// ---------------------------------------------------------------------------
// Kernel A: tiled SGEMM  C[9600,288] = Q[9600,256] * W[256,288] + bias
// Double-buffered smem, one sync per chunk, micro-tile 8M x 3N, f32x2 FMAs.
// ---------------------------------------------------------------------------
__global__ __launch_bounds__(256, 3)
void gemm_kernel(const float* __restrict__ q,
                 const float* __restrict__ Woff,    // (256,192)
                 const float* __restrict__ boff,
                 const float* __restrict__ Wattn,   // (256,96)
                 const float* __restrict__ battn)
{
    const int t   = threadIdx.x;
    const int bm0 = blockIdx.x * BM;
    const int bn  = blockIdx.y;                  // 0,1 -> Woff halves; 2 -> Wattn

    __shared__ __align__(16) float Qs[2][BK * QS_STRIDE];
    __shared__ float Ws[2][BK * BN];

    const float* Wg; int wstride; const float* bg;
    if (bn < 2) { Wg = Woff + bn * BN; wstride = NOFF; bg = boff + bn * BN; }
    else        { Wg = Wattn;          wstride = NATT; bg = battn; }

    const int tn = t & 31;           // col group lane
    const int tm = t >> 5;           // row group (0..7), 8 rows each

    int wk[6], wn[6];
    #pragma unroll
    for (int i = 0; i < 6; i++) {
        const int flat = t + i * 256;
        wk[i] = flat / BN;
        wn[i] = flat - wk[i] * BN;
    }
    const int qr  = t >> 2;          // row 0..63
    const int qc4 = t & 3;           // k-chunk-of-4

    ull acc[3][4];
    #pragma unroll
    for (int j = 0; j < 3; j++) {
        const float b = bg[tn + 32 * j];
        const ull b2 = pack2(b, b);
        #pragma unroll
        for (int pi = 0; pi < 4; pi++) acc[j][pi] = b2;
    }

    // preload chunk 0 and store into buffer 0
    float4 rq = *(const float4*)(q + (size_t)(bm0 + qr) * DM + qc4 * 4);
    float rw[6];
    #pragma unroll
    for (int i = 0; i < 6; i++) rw[i] = Wg[wk[i] * wstride + wn[i]];

    Qs[0][(qc4 * 4 + 0) * QS_STRIDE + qr] = rq.x;
    Qs[0][(qc4 * 4 + 1) * QS_STRIDE + qr] = rq.y;
    Qs[0][(qc4 * 4 + 2) * QS_STRIDE + qr] = rq.z;
    Qs[0][(qc4 * 4 + 3) * QS_STRIDE + qr] = rq.w;
    #pragma unroll
    for (int i = 0; i < 6; i++) Ws[0][wk[i] * BN + wn[i]] = rw[i];
    __syncthreads();

    const int NCH = DM / BK;         // 16 chunks
    for (int ch = 0; ch < NCH; ch++) {
        const int cur = ch & 1;

        // prefetch next chunk into registers (overlaps compute below)
        if (ch + 1 < NCH) {
            const int k0 = (ch + 1) * BK;
            rq = *(const float4*)(q + (size_t)(bm0 + qr) * DM + k0 + qc4 * 4);
            #pragma unroll
            for (int i = 0; i < 6; i++) rw[i] = Wg[(k0 + wk[i]) * wstride + wn[i]];
        }

        // compute from current buffer
        #pragma unroll
        for (int kk = 0; kk < BK; kk++) {
            const float* qrow = Qs[cur] + kk * QS_STRIDE + tm * 8;
            const ulonglong2 qa = *(const ulonglong2*)qrow;
            const ulonglong2 qb = *(const ulonglong2*)(qrow + 4);
            #pragma unroll
            for (int j = 0; j < 3; j++) {
                const float w = Ws[cur][kk * BN + tn + 32 * j];
                const ull  wp = pack2(w, w);
                acc[j][0] = fma2(qa.x, wp, acc[j][0]);
                acc[j][1] = fma2(qa.y, wp, acc[j][1]);
                acc[j][2] = fma2(qb.x, wp, acc[j][2]);
                acc[j][3] = fma2(qb.y, wp, acc[j][3]);
            }
        }

        // store prefetched chunk into the other buffer
        if (ch + 1 < NCH) {
            const int nxt = cur ^ 1;
            Qs[nxt][(qc4 * 4 + 0) * QS_STRIDE + qr] = rq.x;
            Qs[nxt][(qc4 * 4 + 1) * QS_STRIDE + qr] = rq.y;
            Qs[nxt][(qc4 * 4 + 2) * QS_STRIDE + qr] = rq.z;
            Qs[nxt][(qc4 * 4 + 3) * QS_STRIDE + qr] = rq.w;
            #pragma unroll
            for (int i = 0; i < 6; i++) Ws[nxt][wk[i] * BN + wn[i]] = rw[i];
            __syncthreads();
        }
    }

    // epilogue
    #pragma unroll
    for (int j = 0; j < 3; j++) {
        const int n = bn * BN + tn + 32 * j;
        #pragma unroll
        for (int pi = 0; pi < 4; pi++) {
            float lo, hi; unpack2(acc[j][pi], lo, hi);
            const int m = bm0 + tm * 8 + 2 * pi;
            g_res[(size_t)m       * NCOL + n] = lo;
            g_res[(size_t)(m + 1) * NCOL + n] = hi;
        }
    }
}

// ---------------------------------------------------------------------------
// Kernel B: softmax + sampling descriptors. One thread per (bq, h).
// ---------------------------------------------------------------------------
__global__ __launch_bounds__(256)
void desc_kernel(const float* __restrict__ ref)    // (B,Lq,1,4)
{
    const int tid = blockIdx.x * blockDim.x + threadIdx.x;
    if (tid >= B_ * LQ * NH) return;
    const int bq = tid >> 3;
    const int h  = tid & 7;
    const int b  = bq / LQ;

    const float4 r4 = __ldg((const float4*)(ref + (size_t)bq * 4));
    const float* row = g_res + (size_t)bq * NCOL;

    float a[TOTAL];
    float m = -1e30f;
    #pragma unroll
    for (int p = 0; p < TOTAL; p++) { a[p] = row[NOFF + h * TOTAL + p]; m = fmaxf(m, a[p]); }
    float s = 0.f;
    #pragma unroll
    for (int p = 0; p < TOTAL; p++) { a[p] = __expf(a[p] - m); s += a[p]; }
    const float inv = 1.0f / s;

    const int dbase = tid * TOTAL;
    #pragma unroll
    for (int p = 0; p < TOTAL; p++) {
        const float offx = row[h * (TOTAL * 2) + 2 * p];
        const float offy = row[h * (TOTAL * 2) + 2 * p + 1];
        const float wt   = a[p] * inv;

        const float lx = fmaf(offx * 0.125f, r4.z, r4.x);
        const float ly = fmaf(offy * 0.125f, r4.w, r4.y);

        const int lvl = p >> 2;
        const int W   = 80 >> lvl;
        const int st  = (lvl == 0) ? 0 : ((lvl == 1) ? 6400 : 8000);

        const float ix = lx * (float)W - 0.5f;
        const float iy = ly * (float)W - 0.5f;
        const float fix = floorf(ix);
        const float fiy = floorf(iy);
        const int x0 = (int)fix, y0 = (int)fiy;
        const float fx = ix - fix;
        const float fy = iy - fiy;

        const bool vx0 = (x0 >= 0)  & (x0 < W);
        const bool vx1 = (x0 >= -1) & (x0 < W - 1);
        const bool vy0 = (y0 >= 0)  & (y0 < W);
        const bool vy1 = (y0 >= -1) & (y0 < W - 1);

        const int xc0 = min(max(x0, 0), W - 1);
        const int yc0 = min(max(y0, 0), W - 1);

        int bflag = (b * S_ + st + yc0 * W + xc0) * DM;
        if (vx0 & vx1) bflag |= 1;
        if (vy0 & vy1) bflag |= 2;

        const float fx0 = vx0 ? (1.f - fx) : 0.f;
        const float fx1 = vx1 ? fx         : 0.f;
        const float fy0 = (vy0 ? (1.f - fy) : 0.f) * wt;
        const float fy1 = (vy1 ? fy         : 0.f) * wt;

        float4 wq;
        wq.x = fx0 * fy0;   // w00
        wq.y = fx1 * fy0;   // w01
        wq.z = fx0 * fy1;   // w10
        wq.w = fx1 * fy1;   // w11

        g_bflag[dbase + p] = bflag;
        g_wquad[dbase + p] = wq;
    }
}

// ---------------------------------------------------------------------------
// Kernel C: gather. One warp per (bq, h). Lane = 8*corner + r; the 8 lanes of
// a corner group load that corner's full 32 channels as ONE float4 each ->
// one LDG.128 instruction covers all 4 corners. Per-lane partial accumulation,
// single float4 butterfly reduction at the end, STG.128 by lanes 0..7.
// ---------------------------------------------------------------------------
__global__ __launch_bounds__(256)
void sample_kernel(const float* __restrict__ val,   // input_flatten (B,S,256)
                   float* __restrict__ out)
{
    __shared__ int   sbf[8 * TOTAL];
    __shared__ float swt[8 * TOTAL * 4];   // [task][pt][corner]

    const int t     = threadIdx.x;
    const int task0 = blockIdx.x * 8;

    if (t < 8 * TOTAL) {
        sbf[t] = __ldg(&g_bflag[task0 * TOTAL + t]);
        const float4 wq = __ldg(&g_wquad[task0 * TOTAL + t]);
        swt[t * 4 + 0] = wq.x;
        swt[t * 4 + 1] = wq.y;
        swt[t * 4 + 2] = wq.z;
        swt[t * 4 + 3] = wq.w;
    }
    __syncthreads();

    const int w    = t >> 5;
    const int lane = t & 31;
    const int task = task0 + w;
    const int h    = task & 7;

    const int g = lane >> 3;        // corner 0..3
    const int r = lane & 7;         // channel quad 0..7

    const float* vch = val + h * HD + 4 * r;   // channel base for this lane

    float4 acc = make_float4(0.f, 0.f, 0.f, 0.f);

    #pragma unroll
    for (int p = 0; p < TOTAL; p++) {
        const int lvl = p >> 2;
        const int dyv = (80 >> lvl) * DM;

        const int bf   = sbf[w * TOTAL + p];
        const int base = bf & ~255;
        const int dx   = ((bf & 1) & (g & 1))  ? DM  : 0;
        const int dy   = ((bf & 2) && (g >= 2)) ? dyv : 0;

        const float wg = swt[(w * TOTAL + p) * 4 + g];
        const float4 v = __ldg((const float4*)(vch + base + dx + dy));

        acc.x = fmaf(wg, v.x, acc.x);
        acc.y = fmaf(wg, v.y, acc.y);
        acc.z = fmaf(wg, v.z, acc.z);
        acc.w = fmaf(wg, v.w, acc.w);
    }

    // reduce across the 4 corner groups (lanes r, 8+r, 16+r, 24+r)
    #pragma unroll
    for (int mask = 8; mask <= 16; mask <<= 1) {
        acc.x += __shfl_xor_sync(0xffffffffu, acc.x, mask);
        acc.y += __shfl_xor_sync(0xffffffffu, acc.y, mask);
        acc.z += __shfl_xor_sync(0xffffffffu, acc.z, mask);
        acc.w += __shfl_xor_sync(0xffffffffu, acc.w, mask);
    }

    if (lane < 8)
        *(float4*)(out + (size_t)(task >> 3) * DM + h * HD + 4 * lane) = acc;
}

// ---------------------------------------------------------------------------
// Launch
// ---------------------------------------------------------------------------
extern "C" void kernel_launch(void* const* d_in, const int* in_sizes, int n_in,
                              void* d_out, int out_size)
{
    const float* query = (const float*)d_in[0];
    const float* ref   = (const float*)d_in[1];
    const float* value = (const float*)d_in[2];
    const float* Woff  = (const float*)d_in[3];
    const float* boff  = (const float*)d_in[4];
    const float* Wattn = (const float*)d_in[5];
    const float* battn = (const float*)d_in[6];
    float* out = (float*)d_out;

    dim3 ggrid(B_ * LQ / BM, 3);                     // 150 x 3
    gemm_kernel<<<ggrid, 256>>>(query, Woff, boff, Wattn, battn);

    desc_kernel<<<(B_ * LQ * NH + 255) / 256, 256>>>(ref);

    sample_kernel<<<B_ * LQ, 256>>>(value, out);     // 9600 blocks, 8 tasks each
}